// round 13
// baseline (speedup 1.0000x reference)
#include <cuda_runtime.h>
#include <cuda_bf16.h>
#include <cstdint>

// ---------------------------------------------------------------------------
// ResidualLogitAdapter — heterogeneous fused pipeline v5 for GB300 (sm_103)
//   Kernel A (prep):  W1/W2 -> bf16 transposed (tiny)
//   Kernel B (fused, grid=2048):
//     odd  blockIdx: COPY CTA — out = z for 128 rows, SKIPPING the in-domain
//                    16 float4s per row (gemm owns those columns).
//     even blockIdx: GEMM CTA — z-gather + conf stats (computed locally,
//                    latency hidden under feats staging) + MLP via ldmatrix
//                    MMA; epilogue writes out[in-domain] = z + dz.
//   Copy CTAs saturate DRAM while gemm CTAs use tensor/LDS on the same SMs.
// ---------------------------------------------------------------------------

namespace {

constexpr int ROWS_PER_CTA = 128;
constexpr int THREADS      = 256;
constexpr int N_ROWS       = 131072;
constexpr int N_WORK       = N_ROWS / ROWS_PER_CTA;   // 1024
constexpr int N_CTAS       = N_WORK * 2;              // 2048 (copy+gemm pairs)

// smem layout for gemm role (bytes); copy role uses only OFF_DOM
constexpr unsigned OFF_CF    = 0;         // 128 float4 (pmax,ent,marg,alpha) 2048
constexpr unsigned OFF_DOM   = 2048;      // 128 ints (domain col offset)     512
constexpr unsigned OFF_B1V   = 2560;      // 128 floats (b1)                  512
constexpr unsigned OFF_W256  = 3072;      // 128 floats                       512
constexpr unsigned OFF_W257  = 3584;      // 128 floats                       512
constexpr unsigned OFF_W258  = 4096;      // 128 floats                       512
constexpr unsigned OFF_B2V   = 4608;      // 64 floats                        256
constexpr unsigned OFF_SHA   = 8192;      // 4 chunks x [128 x 128B]        65536
constexpr unsigned OFF_SHB   = 73728;     // 2 chunks x [128 x 128B]        32768
constexpr unsigned SMEM_TOTAL = 106496;   // 104 KB -> 2 CTAs/SM

// Device-global scratch (no allocations allowed)
__device__ __nv_bfloat16 g_W1T[128 * 256];        // [h][f] = W1[f][h], f<256
__device__ __nv_bfloat16 g_W2T[64 * 128];         // [n][h] = W2[h][n]

__device__ __forceinline__ unsigned swz(unsigned o) { return o ^ ((o >> 3) & 0x70u); }

__device__ __forceinline__ void mma16816(float c[4], const unsigned a[4],
                                         unsigned b0, unsigned b1) {
    asm volatile(
        "mma.sync.aligned.m16n8k16.row.col.f32.bf16.bf16.f32 "
        "{%0,%1,%2,%3}, {%4,%5,%6,%7}, {%8,%9}, {%0,%1,%2,%3};"
        : "+f"(c[0]), "+f"(c[1]), "+f"(c[2]), "+f"(c[3])
        : "r"(a[0]), "r"(a[1]), "r"(a[2]), "r"(a[3]), "r"(b0), "r"(b1));
}

__device__ __forceinline__ void ldsm_x4(unsigned r[4], unsigned addr) {
    asm volatile(
        "ldmatrix.sync.aligned.m8n8.x4.shared.b16 {%0,%1,%2,%3}, [%4];"
        : "=r"(r[0]), "=r"(r[1]), "=r"(r[2]), "=r"(r[3]) : "r"(addr));
}

// ------------------------------ prep kernel --------------------------------

__global__ void prep_kernel(const float* __restrict__ W1, const float* __restrict__ W2) {
    int i = blockIdx.x * blockDim.x + threadIdx.x;
    if (i < 128 * 256) {
        int h = i >> 8, f = i & 255;
        g_W1T[i] = __float2bfloat16(W1[f * 128 + h]);
    }
    int i2 = i - 128 * 256;
    if (i2 >= 0 && i2 < 64 * 128) {
        int n = i2 >> 7, h = i2 & 127;
        g_W2T[i2] = __float2bfloat16(W2[h * 64 + n]);
    }
}

// ------------------------------ fused kernel -------------------------------

__global__ void __launch_bounds__(THREADS, 2)
fused_kernel(const float* __restrict__ z, const float* __restrict__ feats,
             const float* __restrict__ W1, const float* __restrict__ b1,
             const float* __restrict__ b2, const float* __restrict__ alphas,
             const int* __restrict__ dom, float* __restrict__ out) {
    extern __shared__ char smem[];
    const int tid = threadIdx.x;
    const int work = blockIdx.x >> 1;
    const int row0 = work * ROWS_PER_CTA;

    // =================== COPY role (odd blockIdx) ===================
    if (blockIdx.x & 1) {
        int* domC = (int*)(smem + OFF_DOM);
        if (tid < 128) domC[tid] = dom[row0 + tid] * 16;   // float4 units
        __syncthreads();
        const float4* zin  = (const float4*)z + (size_t)row0 * 128;
        float4*       outv = (float4*)out + (size_t)row0 * 128;
#pragma unroll 8
        for (int i = tid; i < ROWS_PER_CTA * 128; i += THREADS) {
            const float4 v = zin[i];
            const int r = i >> 7, c4 = i & 127;
            if ((unsigned)(c4 - domC[r]) >= 16u)   // gemm owns in-domain cols
                outv[i] = v;
        }
        return;
    }

    // =================== GEMM role (even blockIdx) ===================
    const int wid = tid >> 5;
    const int lid = tid & 31;
    const int gid = lid >> 2;    // mma group id (0..7)
    const int tid4 = lid & 3;    // mma thread-in-group (0..3)
    const unsigned sbase = (unsigned)__cvta_generic_to_shared(smem);

    float4* cF    = (float4*)(smem + OFF_CF);
    int*   domS   = (int*)(smem + OFF_DOM);
    float* b1S    = (float*)(smem + OFF_B1V);
    float* w256S  = (float*)(smem + OFF_W256);
    float* w257S  = (float*)(smem + OFF_W257);
    float* w258S  = (float*)(smem + OFF_W258);
    float* b2S    = (float*)(smem + OFF_B2V);

    // ---- Phase A: issue this warp's 16-row z-gather (32 LDG in flight).
    const int rbase = wid * 16;
    float x0[16], x1[16];
    int offr[16];
#pragma unroll
    for (int i = 0; i < 16; i++) {
        const int grow = row0 + rbase + i;
        offr[i] = dom[grow] * 64;                // warp-uniform
        const float* zr = z + (size_t)grow * 512 + offr[i];
        x0[i] = zr[lid];
        x1[i] = zr[lid + 32];
    }

    // ---- Phase B: stage ALL of feats (4 chunks, 64KB) -> SHA; hides gather.
    {
        const float4* fv = (const float4*)feats + (size_t)row0 * 64;
#pragma unroll 4
        for (int j = tid; j < 128 * 64; j += THREADS) {    // groups of 4 floats
            int r = j >> 6, k4 = j & 63;
            float4 v = fv[(size_t)r * 64 + k4];
            unsigned chunk = (unsigned)(k4 >> 4);
            unsigned kb = (unsigned)((k4 & 15) << 3);
            __nv_bfloat162 p0 = __floats2bfloat162_rn(v.x, v.y);
            __nv_bfloat162 p1 = __floats2bfloat162_rn(v.z, v.w);
            uint2 u;
            u.x = *(unsigned*)&p0; u.y = *(unsigned*)&p1;
            *(uint2*)(smem + OFF_SHA + chunk * 16384u + swz((unsigned)r * 128u + kb)) = u;
        }
        if (tid < 128) {
            b1S[tid]   = b1[tid];
            w256S[tid] = W1[256 * 128 + tid];
            w257S[tid] = W1[257 * 128 + tid];
            w258S[tid] = W1[258 * 128 + tid];
            if (tid < 64) b2S[tid] = b2[tid];
        }
    }

    // ---- Phase C: conf stats (16 independent shuffle chains; ILP hides lat)
#pragma unroll
    for (int i = 0; i < 16; i++) {
        const int r = rbase + i;
        float m1 = fmaxf(x0[i], x1[i]);
        float m2 = fminf(x0[i], x1[i]);
#pragma unroll
        for (int s = 16; s > 0; s >>= 1) {
            float o1 = __shfl_xor_sync(0xffffffffu, m1, s);
            float o2 = __shfl_xor_sync(0xffffffffu, m2, s);
            float hi = fmaxf(m1, o1);
            float lo = fmaxf(fminf(m1, o1), fmaxf(m2, o2));
            m1 = hi; m2 = lo;
        }
        float e0 = expf(x0[i] - m1), e1 = expf(x1[i] - m1);
        float S = e0 + e1;
        float T = e0 * (x0[i] - m1) + e1 * (x1[i] - m1);
#pragma unroll
        for (int s = 16; s > 0; s >>= 1) {
            S += __shfl_xor_sync(0xffffffffu, S, s);
            T += __shfl_xor_sync(0xffffffffu, T, s);
        }
        if (lid == 0) {
            const float inv = 1.0f / S;
            float4 cf;
            cf.x = inv;                          // p_max
            cf.y = logf(S) - T * inv;            // entropy
            cf.z = (1.0f - expf(m2 - m1)) * inv; // margin
            cf.w = alphas[offr[i] >> 6];
            cF[r] = cf;
            domS[r] = offr[i];
        }
    }

    // ldmatrix lane-address components (within-chunk byte offsets, pre-swizzle)
    const int mrow0 = (wid & 3) * 32;
    const int ncol0 = (wid >> 2) * 64;
    const unsigned laneR  = (unsigned)(lid & 15);
    const unsigned laneHi = (unsigned)(lid >> 4);              // 0/1
    const unsigned offA0 = (unsigned)(mrow0 + laneR) * 128u + laneHi * 16u;
    const unsigned offA1 = offA0 + 16u * 128u;
    const unsigned nLane  = laneHi * 8u + (unsigned)(lid & 7);
    const unsigned colHiB = ((unsigned)(lid >> 3) & 1u) * 16u;

    // GEMM1 accumulators persist across both K-halves.
    float acc[2][8][4];
#pragma unroll
    for (int mi = 0; mi < 2; mi++)
#pragma unroll
        for (int ni = 0; ni < 8; ni++)
#pragma unroll
            for (int q = 0; q < 4; q++) acc[mi][ni][q] = 0.0f;

    // ---- GEMM1 over two K-halves; B (W1T, L2-hot) restaged per half in SHB.
#pragma unroll 1
    for (int half = 0; half < 2; half++) {
        const uint2* w1t = (const uint2*)g_W1T + half * 32;   // 4 bf16 per uint2
#pragma unroll 4
        for (int j = tid; j < 128 * 32; j += THREADS) {
            int hr = j >> 5, k4 = j & 31;
            uint2 u = w1t[(size_t)hr * 64 + k4];
            unsigned chunk = (unsigned)(k4 >> 4);
            unsigned kb = (unsigned)((k4 & 15) << 3);
            *(uint2*)(smem + OFF_SHB + chunk * 16384u + swz((unsigned)hr * 128u + kb)) = u;
        }
        __syncthreads();

        // accumulate this K-half (A chunks half*2 + kc)
#pragma unroll
        for (int kc = 0; kc < 2; kc++) {
            const unsigned aB = sbase + OFF_SHA + (unsigned)(half * 2 + kc) * 16384u;
            const unsigned bB = sbase + OFF_SHB + (unsigned)kc * 16384u;
#pragma unroll
            for (int ks = 0; ks < 4; ks++) {
                const unsigned kt = (unsigned)ks * 32u;
                unsigned a0[4], a1[4];
                ldsm_x4(a0, aB + swz(offA0 + kt));
                ldsm_x4(a1, aB + swz(offA1 + kt));
#pragma unroll
                for (int j = 0; j < 4; j++) {
                    unsigned bb[4];
                    const unsigned offB =
                        (unsigned)(ncol0 + j * 16) * 128u + nLane * 128u + colHiB;
                    ldsm_x4(bb, bB + swz(offB + kt));
                    mma16816(acc[0][2 * j],     a0, bb[0], bb[1]);
                    mma16816(acc[1][2 * j],     a1, bb[0], bb[1]);
                    mma16816(acc[0][2 * j + 1], a0, bb[2], bb[3]);
                    mma16816(acc[1][2 * j + 1], a1, bb[2], bb[3]);
                }
            }
        }
        __syncthreads();   // done reading SHB before restaging / reuse
    }

    // ---- Epilogue1: A2 = bf16(relu(h_pre + b1 + c @ W1[256:259])) -> SHB.
    //      Concurrently stage B2 (W2T, 16KB) -> SHA (chunks 0,1 reusable).
    {
#pragma unroll
        for (int mi = 0; mi < 2; mi++) {
            const int rA = mrow0 + mi * 16 + gid;      // rows rA and rA+8
            const float4 cfa = cF[rA];
            const float4 cfb = cF[rA + 8];
#pragma unroll
            for (int ni = 0; ni < 8; ni++) {
                const int j = ncol0 + ni * 8 + tid4 * 2;    // global h col (even)
                const float bj0 = b1S[j],     bj1 = b1S[j + 1];
                const float wa0 = w256S[j],   wa1 = w256S[j + 1];
                const float wb0 = w257S[j],   wb1 = w257S[j + 1];
                const float wc0 = w258S[j],   wc1 = w258S[j + 1];
                float v0 = acc[mi][ni][0] + bj0 + cfa.x * wa0 + cfa.y * wb0 + cfa.z * wc0;
                float v1 = acc[mi][ni][1] + bj1 + cfa.x * wa1 + cfa.y * wb1 + cfa.z * wc1;
                float v2 = acc[mi][ni][2] + bj0 + cfb.x * wa0 + cfb.y * wb0 + cfb.z * wc0;
                float v3 = acc[mi][ni][3] + bj1 + cfb.x * wa1 + cfb.y * wb1 + cfb.z * wc1;
                v0 = fmaxf(v0, 0.0f); v1 = fmaxf(v1, 0.0f);
                v2 = fmaxf(v2, 0.0f); v3 = fmaxf(v3, 0.0f);
                __nv_bfloat162 pA = __floats2bfloat162_rn(v0, v1);
                __nv_bfloat162 pB = __floats2bfloat162_rn(v2, v3);
                const unsigned a2chunk = (unsigned)(wid >> 2) * 16384u;
                const unsigned jb = (unsigned)((ni * 8 + tid4 * 2) * 2);
                *(unsigned*)(smem + OFF_SHB + a2chunk +
                             swz((unsigned)rA * 128u + jb)) = *(unsigned*)&pA;
                *(unsigned*)(smem + OFF_SHB + a2chunk +
                             swz((unsigned)(rA + 8) * 128u + jb)) = *(unsigned*)&pB;
            }
        }
        const uint2* w2t = (const uint2*)g_W2T;
        for (int j = tid; j < 64 * 32; j += THREADS) {
            int nr = j >> 5, k4 = j & 31;
            uint2 u = w2t[j];
            unsigned chunk = (unsigned)(k4 >> 4);
            unsigned kb = (unsigned)((k4 & 15) << 3);
            *(uint2*)(smem + OFF_SHA + chunk * 8192u + swz((unsigned)nr * 128u + kb)) = u;
        }
    }
    __syncthreads();

    // ---- GEMM2  dz[128,64] = h[128,128] @ W2;  A2 in SHB, W2T in SHA.
    {
        const int ncol2 = (wid >> 2) * 32;
        float acc2[2][4][4];
#pragma unroll
        for (int mi = 0; mi < 2; mi++)
#pragma unroll
            for (int ni = 0; ni < 4; ni++)
#pragma unroll
                for (int q = 0; q < 4; q++) acc2[mi][ni][q] = 0.0f;

        // Prefetch epilogue2 z-rereads so their latency hides under the MMAs.
        float2 pzA[2][4], pzB[2][4];
#pragma unroll
        for (int mi = 0; mi < 2; mi++) {
            const int rA = mrow0 + mi * 16 + gid;
            const float* zA = z + (size_t)(row0 + rA) * 512 + domS[rA];
            const float* zB = z + (size_t)(row0 + rA + 8) * 512 + domS[rA + 8];
#pragma unroll
            for (int ni = 0; ni < 4; ni++) {
                const int j = ncol2 + ni * 8 + tid4 * 2;
                pzA[mi][ni] = *(const float2*)(zA + j);
                pzB[mi][ni] = *(const float2*)(zB + j);
            }
        }

#pragma unroll
        for (int kc = 0; kc < 2; kc++) {
            const unsigned aB = sbase + OFF_SHB + (unsigned)kc * 16384u;
            const unsigned bB = sbase + OFF_SHA + (unsigned)kc * 8192u;
#pragma unroll
            for (int ks = 0; ks < 4; ks++) {
                const unsigned kt = (unsigned)ks * 32u;
                unsigned a0[4], a1[4];
                ldsm_x4(a0, aB + swz(offA0 + kt));
                ldsm_x4(a1, aB + swz(offA1 + kt));
#pragma unroll
                for (int j = 0; j < 2; j++) {
                    unsigned bb[4];
                    const unsigned offB =
                        (unsigned)(ncol2 + j * 16) * 128u + nLane * 128u + colHiB;
                    ldsm_x4(bb, bB + swz(offB + kt));
                    mma16816(acc2[0][2 * j],     a0, bb[0], bb[1]);
                    mma16816(acc2[1][2 * j],     a1, bb[0], bb[1]);
                    mma16816(acc2[0][2 * j + 1], a0, bb[2], bb[3]);
                    mma16816(acc2[1][2 * j + 1], a1, bb[2], bb[3]);
                }
            }
        }

        // ---- Epilogue2: out[in-domain] = z + (dz + b2) * alpha.
        //      (copy CTAs never write these columns -> no ordering needed)
#pragma unroll
        for (int mi = 0; mi < 2; mi++) {
            const int rA = mrow0 + mi * 16 + gid;
            const float alA = cF[rA].w;
            const float alB = cF[rA + 8].w;
            float* outA = out + (size_t)(row0 + rA) * 512 + domS[rA];
            float* outB = out + (size_t)(row0 + rA + 8) * 512 + domS[rA + 8];
#pragma unroll
            for (int ni = 0; ni < 4; ni++) {
                const int j = ncol2 + ni * 8 + tid4 * 2;
                const float bj0 = b2S[j], bj1 = b2S[j + 1];
                float2 oA, oB;
                oA.x = pzA[mi][ni].x + (acc2[mi][ni][0] + bj0) * alA;
                oA.y = pzA[mi][ni].y + (acc2[mi][ni][1] + bj1) * alA;
                oB.x = pzB[mi][ni].x + (acc2[mi][ni][2] + bj0) * alB;
                oB.y = pzB[mi][ni].y + (acc2[mi][ni][3] + bj1) * alB;
                *(float2*)(outA + j) = oA;
                *(float2*)(outB + j) = oB;
            }
        }
    }
}

}  // namespace

// ------------------------------ launch -------------------------------------

extern "C" void kernel_launch(void* const* d_in, const int* in_sizes, int n_in,
                              void* d_out, int out_size) {
    const float* z      = (const float*)d_in[0];
    const float* feats  = (const float*)d_in[1];
    const float* W1     = (const float*)d_in[2];
    const float* b1     = (const float*)d_in[3];
    const float* W2     = (const float*)d_in[4];
    const float* b2     = (const float*)d_in[5];
    const float* alphas = (const float*)d_in[6];
    const int*   dom    = (const int*)d_in[7];
    float* out = (float*)d_out;

    cudaFuncSetAttribute(fused_kernel, cudaFuncAttributeMaxDynamicSharedMemorySize,
                         SMEM_TOTAL);

    prep_kernel<<<(128 * 256 + 64 * 128 + 255) / 256, 256>>>(W1, W2);
    fused_kernel<<<N_CTAS, THREADS, SMEM_TOTAL>>>(z, feats, W1, b1, b2,
                                                  alphas, dom, out);
}

// round 14
// speedup vs baseline: 1.2451x; 1.2451x over previous
#include <cuda_runtime.h>
#include <cuda_bf16.h>
#include <cstdint>

// ---------------------------------------------------------------------------
// ResidualLogitAdapter — split pipeline v6 for GB300 (sm_103)
//   Kernel A (copyconf): out = z stream (2 float4/thread), SKIPPING the
//                        in-domain 16 float4s per row (gemm rewrites them);
//                        per-row softmax conf stats -> g_conf; first 160
//                        blocks also build bf16 transposed weights.
//   Kernel B (gemm):     MLP using g_conf; W1T/W2T staged via cp.async with
//                        a 2-deep chunk pipeline (latency hidden under MMAs);
//                        fragment loads via ldmatrix; epilogue z-rereads
//                        prefetched; epilogue writes out[in-domain] = z + dz.
// ---------------------------------------------------------------------------

namespace {

constexpr int ROWS_PER_CTA = 128;
constexpr int THREADS      = 256;
constexpr int N_ROWS       = 131072;
constexpr int N_CTAS       = N_ROWS / ROWS_PER_CTA;   // 1024

// smem layout for gemm kernel (bytes)
constexpr unsigned OFF_CF    = 0;         // 128 float4 (pmax,ent,marg,alpha) 2048
constexpr unsigned OFF_DOM   = 2048;      // 128 ints (domain col offset)     512
constexpr unsigned OFF_B1V   = 2560;      // 128 floats (b1)                  512
constexpr unsigned OFF_W256  = 3072;      // 128 floats                       512
constexpr unsigned OFF_W257  = 3584;      // 128 floats                       512
constexpr unsigned OFF_W258  = 4096;      // 128 floats                       512
constexpr unsigned OFF_B2V   = 4608;      // 64 floats                        256
constexpr unsigned OFF_SHA   = 8192;      // 4 chunks x [128 x 128B]        65536
constexpr unsigned OFF_SHB   = 73728;     // 2 chunks x [128 x 128B]        32768
constexpr unsigned SMEM_TOTAL = 106496;   // 104 KB -> 2 CTAs/SM

// Device-global scratch (no allocations allowed)
__device__ __nv_bfloat16 g_W1T[128 * 256];        // [h][f] = W1[f][h], f<256
__device__ __nv_bfloat16 g_W2T[64 * 128];         // [n][h] = W2[h][n]
__device__ __align__(16) float4 g_conf[N_ROWS];   // 2 MB: pmax,ent,marg,alpha

constexpr int PREP_ELEMS  = 128 * 256 + 64 * 128;   // 40960
constexpr int PREP_BLOCKS = PREP_ELEMS / 256;       // 160

__device__ __forceinline__ unsigned swz(unsigned o) { return o ^ ((o >> 3) & 0x70u); }

__device__ __forceinline__ void mma16816(float c[4], const unsigned a[4],
                                         unsigned b0, unsigned b1) {
    asm volatile(
        "mma.sync.aligned.m16n8k16.row.col.f32.bf16.bf16.f32 "
        "{%0,%1,%2,%3}, {%4,%5,%6,%7}, {%8,%9}, {%0,%1,%2,%3};"
        : "+f"(c[0]), "+f"(c[1]), "+f"(c[2]), "+f"(c[3])
        : "r"(a[0]), "r"(a[1]), "r"(a[2]), "r"(a[3]), "r"(b0), "r"(b1));
}

__device__ __forceinline__ void ldsm_x4(unsigned r[4], unsigned addr) {
    asm volatile(
        "ldmatrix.sync.aligned.m8n8.x4.shared.b16 {%0,%1,%2,%3}, [%4];"
        : "=r"(r[0]), "=r"(r[1]), "=r"(r[2]), "=r"(r[3]) : "r"(addr));
}

__device__ __forceinline__ void cp16(unsigned dst, const void* src) {
    asm volatile("cp.async.ca.shared.global [%0], [%1], 16;"
                 :: "r"(dst), "l"(src) : "memory");
}
__device__ __forceinline__ void cp_commit() {
    asm volatile("cp.async.commit_group;" ::: "memory");
}
template <int N>
__device__ __forceinline__ void cp_wait() {
    asm volatile("cp.async.wait_group %0;" :: "n"(N) : "memory");
}

// --------------------------- copy + conf kernel ----------------------------
// grid = 32768; each thread handles TWO float4 elements (t and t+256).
// In-domain elements: conf reduction only (store skipped — gemm owns them).

__device__ __forceinline__ void handle_elem(const float4 v, size_t t,
                                            const int* __restrict__ dom,
                                            const float* __restrict__ alphas,
                                            float4* __restrict__ out4) {
    const int r  = (int)(t >> 7);
    const int c4 = (int)(t & 127u);
    const int d = dom[r];
    const int off4 = d * 16;
    const int rel = c4 - off4;
    if ((unsigned)rel >= 16u) {
        out4[t] = v;                      // out-of-domain: plain copy
        return;
    }
    // in-domain: conf reduction across the 16-thread (half-warp) group
    const unsigned mask = 0xFFFFu << (off4 & 16);
    float hi1 = fmaxf(v.x, v.y), lo1 = fminf(v.x, v.y);
    float hi2 = fmaxf(v.z, v.w), lo2 = fminf(v.z, v.w);
    float m1 = fmaxf(hi1, hi2);
    float m2 = fmaxf(fminf(hi1, hi2), fmaxf(lo1, lo2));
#pragma unroll
    for (int s = 8; s > 0; s >>= 1) {
        float o1 = __shfl_xor_sync(mask, m1, s);
        float o2 = __shfl_xor_sync(mask, m2, s);
        float hi = fmaxf(m1, o1);
        float lo = fmaxf(fminf(m1, o1), fmaxf(m2, o2));
        m1 = hi; m2 = lo;
    }
    const float d0 = v.x - m1, d1 = v.y - m1, d2 = v.z - m1, d3 = v.w - m1;
    const float e0 = expf(d0), e1 = expf(d1), e2 = expf(d2), e3 = expf(d3);
    float S = (e0 + e1) + (e2 + e3);
    float T = (e0 * d0 + e1 * d1) + (e2 * d2 + e3 * d3);
#pragma unroll
    for (int s = 8; s > 0; s >>= 1) {
        S += __shfl_xor_sync(mask, S, s);
        T += __shfl_xor_sync(mask, T, s);
    }
    if (rel == 0) {
        const float inv = 1.0f / S;
        float4 cf;
        cf.x = inv;                          // p_max
        cf.y = logf(S) - T * inv;            // entropy
        cf.z = (1.0f - expf(m2 - m1)) * inv; // margin
        cf.w = alphas[d];
        g_conf[r] = cf;
    }
}

__global__ void __launch_bounds__(256)
copyconf_kernel(const float4* __restrict__ z4, const int* __restrict__ dom,
                const float* __restrict__ alphas,
                const float* __restrict__ W1, const float* __restrict__ W2,
                float4* __restrict__ out4) {
    const size_t t0 = (size_t)blockIdx.x * 512u + threadIdx.x;
    const size_t t1 = t0 + 256u;

    const float4 v0 = z4[t0];
    const float4 v1 = z4[t1];
    handle_elem(v0, t0, dom, alphas, out4);
    handle_elem(v1, t1, dom, alphas, out4);

    // folded prep: first PREP_BLOCKS blocks convert weights to bf16 transposed
    if (blockIdx.x < PREP_BLOCKS) {
        int i = blockIdx.x * 256 + threadIdx.x;
        if (i < 128 * 256) {
            int h = i >> 8, f = i & 255;
            g_W1T[i] = __float2bfloat16(W1[f * 128 + h]);
        } else {
            int i2 = i - 128 * 256;           // < 64*128
            int n = i2 >> 7, h = i2 & 127;
            g_W2T[i2] = __float2bfloat16(W2[h * 64 + n]);
        }
    }
}

// ------------------------------ gemm kernel --------------------------------

__global__ void __launch_bounds__(THREADS, 2)
gemm_kernel(const float* __restrict__ z, const float* __restrict__ feats,
            const float* __restrict__ W1, const float* __restrict__ b1,
            const float* __restrict__ b2, const int* __restrict__ dom,
            float* __restrict__ out) {
    extern __shared__ char smem[];
    const int tid = threadIdx.x;
    const int wid = tid >> 5;
    const int lid = tid & 31;
    const int gid = lid >> 2;    // mma group id (0..7)
    const int tid4 = lid & 3;    // mma thread-in-group (0..3)
    const int row0 = blockIdx.x * ROWS_PER_CTA;
    const unsigned sbase = (unsigned)__cvta_generic_to_shared(smem);

    float4* cF    = (float4*)(smem + OFF_CF);
    int*   domS   = (int*)(smem + OFF_DOM);
    float* b1S    = (float*)(smem + OFF_B1V);
    float* w256S  = (float*)(smem + OFF_W256);
    float* w257S  = (float*)(smem + OFF_W257);
    float* w258S  = (float*)(smem + OFF_W258);
    float* b2S    = (float*)(smem + OFF_B2V);

    // ---- Phase 0: small staging (conf, dom, bias/conf-weight vectors)
    if (tid < 128) {
        cF[tid]   = g_conf[row0 + tid];
        domS[tid] = dom[row0 + tid] * 64;
        b1S[tid]   = b1[tid];
        w256S[tid] = W1[256 * 128 + tid];
        w257S[tid] = W1[257 * 128 + tid];
        w258S[tid] = W1[258 * 128 + tid];
        if (tid < 64) b2S[tid] = b2[tid];
    }

    // ---- Stage ALL of feats (K=256, 4 chunks, 64KB) -> SHA, one exposure.
    {
        const float4* fv = (const float4*)feats + (size_t)row0 * 64;
#pragma unroll 4
        for (int j = tid; j < 128 * 64; j += THREADS) {    // groups of 4 floats
            int r = j >> 6, k4 = j & 63;
            float4 v = fv[(size_t)r * 64 + k4];
            unsigned chunk = (unsigned)(k4 >> 4);
            unsigned kb = (unsigned)((k4 & 15) << 3);
            __nv_bfloat162 p0 = __floats2bfloat162_rn(v.x, v.y);
            __nv_bfloat162 p1 = __floats2bfloat162_rn(v.z, v.w);
            uint2 u;
            u.x = *(unsigned*)&p0; u.y = *(unsigned*)&p1;
            *(uint2*)(smem + OFF_SHA + chunk * 16384u + swz((unsigned)r * 128u + kb)) = u;
        }
    }

    // ---- Prefetch W1T chunks 0,1 via cp.async (16B units; SW128 preserves
    //      16B blocks).  Chunk kcg: 1024 units, 4 per thread.
    const char* w1tB = (const char*)g_W1T;
#pragma unroll
    for (int pre = 0; pre < 2; pre++) {
#pragma unroll
        for (int u = 0; u < 4; u++) {
            const int j = tid + u * 256;          // 0..1023
            const unsigned hr  = (unsigned)(j >> 3);
            const unsigned off = (unsigned)(j & 7) * 16u;
            cp16(sbase + OFF_SHB + (unsigned)pre * 16384u + swz(hr * 128u + off),
                 w1tB + hr * 512u + (unsigned)pre * 128u + off);
        }
        cp_commit();
    }

    // ldmatrix lane-address components (within-chunk byte offsets, pre-swizzle)
    const int mrow0 = (wid & 3) * 32;
    const int ncol0 = (wid >> 2) * 64;
    const unsigned laneR  = (unsigned)(lid & 15);
    const unsigned laneHi = (unsigned)(lid >> 4);              // 0/1
    const unsigned offA0 = (unsigned)(mrow0 + laneR) * 128u + laneHi * 16u;
    const unsigned offA1 = offA0 + 16u * 128u;
    const unsigned nLane  = laneHi * 8u + (unsigned)(lid & 7);
    const unsigned colHiB = ((unsigned)(lid >> 3) & 1u) * 16u;

    // GEMM1 accumulators persist across all four K-chunks.
    float acc[2][8][4];
#pragma unroll
    for (int mi = 0; mi < 2; mi++)
#pragma unroll
        for (int ni = 0; ni < 8; ni++)
#pragma unroll
            for (int q = 0; q < 4; q++) acc[mi][ni][q] = 0.0f;

    // ---- GEMM1: 4 K-chunks, 2-deep cp.async pipeline through SHB buffers.
#pragma unroll 1
    for (int kcg = 0; kcg < 4; kcg++) {
        if (kcg < 3) cp_wait<1>(); else cp_wait<0>();
        __syncthreads();   // W1T chunk kcg in its buffer; also covers feats/cF

        const unsigned aB = sbase + OFF_SHA + (unsigned)kcg * 16384u;
        const unsigned bB = sbase + OFF_SHB + (unsigned)(kcg & 1) * 16384u;
#pragma unroll
        for (int ks = 0; ks < 4; ks++) {
            const unsigned kt = (unsigned)ks * 32u;
            unsigned a0[4], a1[4];
            ldsm_x4(a0, aB + swz(offA0 + kt));
            ldsm_x4(a1, aB + swz(offA1 + kt));
#pragma unroll
            for (int j = 0; j < 4; j++) {
                unsigned bb[4];
                const unsigned offB =
                    (unsigned)(ncol0 + j * 16) * 128u + nLane * 128u + colHiB;
                ldsm_x4(bb, bB + swz(offB + kt));
                mma16816(acc[0][2 * j],     a0, bb[0], bb[1]);
                mma16816(acc[1][2 * j],     a1, bb[0], bb[1]);
                mma16816(acc[0][2 * j + 1], a0, bb[2], bb[3]);
                mma16816(acc[1][2 * j + 1], a1, bb[2], bb[3]);
            }
        }
        __syncthreads();   // all warps done reading this buffer

        if (kcg < 2) {     // prefetch chunk kcg+2 into the freed buffer
#pragma unroll
            for (int u = 0; u < 4; u++) {
                const int j = tid + u * 256;
                const unsigned hr  = (unsigned)(j >> 3);
                const unsigned off = (unsigned)(j & 7) * 16u;
                cp16(sbase + OFF_SHB + (unsigned)(kcg & 1) * 16384u +
                         swz(hr * 128u + off),
                     w1tB + hr * 512u + (unsigned)(kcg + 2) * 128u + off);
            }
            cp_commit();
        }
    }

    // ---- Issue W2T cp.async now (dst: SHA chunks 0,1 region — feats dead);
    //      its latency hides under the epilogue-1 ALU below.
    {
        const char* w2tB = (const char*)g_W2T;
#pragma unroll
        for (int u = 0; u < 4; u++) {
            const int j = tid + u * 256;          // 0..1023
            const unsigned nr  = (unsigned)(j >> 4);          // 0..63
            const unsigned c   = ((unsigned)j >> 3) & 1u;     // chunk
            const unsigned off = (unsigned)(j & 7) * 16u;
            cp16(sbase + OFF_SHA + c * 8192u + swz(nr * 128u + off),
                 w2tB + nr * 256u + c * 128u + off);
        }
        cp_commit();
    }

    // ---- Epilogue1: A2 = bf16(relu(h_pre + b1 + c @ W1[256:259])) -> SHB.
    {
#pragma unroll
        for (int mi = 0; mi < 2; mi++) {
            const int rA = mrow0 + mi * 16 + gid;      // rows rA and rA+8
            const float4 cfa = cF[rA];
            const float4 cfb = cF[rA + 8];
#pragma unroll
            for (int ni = 0; ni < 8; ni++) {
                const int j = ncol0 + ni * 8 + tid4 * 2;    // global h col (even)
                const float bj0 = b1S[j],     bj1 = b1S[j + 1];
                const float wa0 = w256S[j],   wa1 = w256S[j + 1];
                const float wb0 = w257S[j],   wb1 = w257S[j + 1];
                const float wc0 = w258S[j],   wc1 = w258S[j + 1];
                float v0 = acc[mi][ni][0] + bj0 + cfa.x * wa0 + cfa.y * wb0 + cfa.z * wc0;
                float v1 = acc[mi][ni][1] + bj1 + cfa.x * wa1 + cfa.y * wb1 + cfa.z * wc1;
                float v2 = acc[mi][ni][2] + bj0 + cfb.x * wa0 + cfb.y * wb0 + cfb.z * wc0;
                float v3 = acc[mi][ni][3] + bj1 + cfb.x * wa1 + cfb.y * wb1 + cfb.z * wc1;
                v0 = fmaxf(v0, 0.0f); v1 = fmaxf(v1, 0.0f);
                v2 = fmaxf(v2, 0.0f); v3 = fmaxf(v3, 0.0f);
                __nv_bfloat162 pA = __floats2bfloat162_rn(v0, v1);
                __nv_bfloat162 pB = __floats2bfloat162_rn(v2, v3);
                const unsigned a2chunk = (unsigned)(wid >> 2) * 16384u;
                const unsigned jb = (unsigned)((ni * 8 + tid4 * 2) * 2);
                *(unsigned*)(smem + OFF_SHB + a2chunk +
                             swz((unsigned)rA * 128u + jb)) = *(unsigned*)&pA;
                *(unsigned*)(smem + OFF_SHB + a2chunk +
                             swz((unsigned)(rA + 8) * 128u + jb)) = *(unsigned*)&pB;
            }
        }
    }
    cp_wait<0>();        // W2T arrived
    __syncthreads();

    // ---- GEMM2  dz[128,64] = h[128,128] @ W2;  A2 in SHB, W2T in SHA.
    {
        const int ncol2 = (wid >> 2) * 32;
        float acc2[2][4][4];
#pragma unroll
        for (int mi = 0; mi < 2; mi++)
#pragma unroll
            for (int ni = 0; ni < 4; ni++)
#pragma unroll
                for (int q = 0; q < 4; q++) acc2[mi][ni][q] = 0.0f;

        // Prefetch epilogue2 z-rereads so their latency hides under the MMAs.
        float2 pzA[2][4], pzB[2][4];
#pragma unroll
        for (int mi = 0; mi < 2; mi++) {
            const int rA = mrow0 + mi * 16 + gid;
            const float* zA = z + (size_t)(row0 + rA) * 512 + domS[rA];
            const float* zB = z + (size_t)(row0 + rA + 8) * 512 + domS[rA + 8];
#pragma unroll
            for (int ni = 0; ni < 4; ni++) {
                const int j = ncol2 + ni * 8 + tid4 * 2;
                pzA[mi][ni] = *(const float2*)(zA + j);
                pzB[mi][ni] = *(const float2*)(zB + j);
            }
        }

#pragma unroll
        for (int kc = 0; kc < 2; kc++) {
            const unsigned aB = sbase + OFF_SHB + (unsigned)kc * 16384u;
            const unsigned bB = sbase + OFF_SHA + (unsigned)kc * 8192u;
#pragma unroll
            for (int ks = 0; ks < 4; ks++) {
                const unsigned kt = (unsigned)ks * 32u;
                unsigned a0[4], a1[4];
                ldsm_x4(a0, aB + swz(offA0 + kt));
                ldsm_x4(a1, aB + swz(offA1 + kt));
#pragma unroll
                for (int j = 0; j < 2; j++) {
                    unsigned bb[4];
                    const unsigned offB =
                        (unsigned)(ncol2 + j * 16) * 128u + nLane * 128u + colHiB;
                    ldsm_x4(bb, bB + swz(offB + kt));
                    mma16816(acc2[0][2 * j],     a0, bb[0], bb[1]);
                    mma16816(acc2[1][2 * j],     a1, bb[0], bb[1]);
                    mma16816(acc2[0][2 * j + 1], a0, bb[2], bb[3]);
                    mma16816(acc2[1][2 * j + 1], a1, bb[2], bb[3]);
                }
            }
        }

        // ---- Epilogue2: out[in-domain] = z + (dz + b2) * alpha.
        //      (copyconf never writes these columns)
#pragma unroll
        for (int mi = 0; mi < 2; mi++) {
            const int rA = mrow0 + mi * 16 + gid;
            const float alA = cF[rA].w;
            const float alB = cF[rA + 8].w;
            float* outA = out + (size_t)(row0 + rA) * 512 + domS[rA];
            float* outB = out + (size_t)(row0 + rA + 8) * 512 + domS[rA + 8];
#pragma unroll
            for (int ni = 0; ni < 4; ni++) {
                const int j = ncol2 + ni * 8 + tid4 * 2;
                const float bj0 = b2S[j], bj1 = b2S[j + 1];
                float2 oA, oB;
                oA.x = pzA[mi][ni].x + (acc2[mi][ni][0] + bj0) * alA;
                oA.y = pzA[mi][ni].y + (acc2[mi][ni][1] + bj1) * alA;
                oB.x = pzB[mi][ni].x + (acc2[mi][ni][2] + bj0) * alB;
                oB.y = pzB[mi][ni].y + (acc2[mi][ni][3] + bj1) * alB;
                *(float2*)(outA + j) = oA;
                *(float2*)(outB + j) = oB;
            }
        }
    }
}

}  // namespace

// ------------------------------ launch -------------------------------------

extern "C" void kernel_launch(void* const* d_in, const int* in_sizes, int n_in,
                              void* d_out, int out_size) {
    const float* z      = (const float*)d_in[0];
    const float* feats  = (const float*)d_in[1];
    const float* W1     = (const float*)d_in[2];
    const float* b1     = (const float*)d_in[3];
    const float* W2     = (const float*)d_in[4];
    const float* b2     = (const float*)d_in[5];
    const float* alphas = (const float*)d_in[6];
    const int*   dom    = (const int*)d_in[7];
    float* out = (float*)d_out;

    cudaFuncSetAttribute(gemm_kernel, cudaFuncAttributeMaxDynamicSharedMemorySize,
                         SMEM_TOTAL);

    copyconf_kernel<<<N_ROWS * 128 / 512, 256>>>((const float4*)z, dom, alphas,
                                                 W1, W2, (float4*)out);
    gemm_kernel<<<N_CTAS, THREADS, SMEM_TOTAL>>>(z, feats, W1, b1, b2, dom, out);
}

// round 15
// speedup vs baseline: 1.2498x; 1.0038x over previous
#include <cuda_runtime.h>
#include <cuda_bf16.h>
#include <cstdint>

// ---------------------------------------------------------------------------
// ResidualLogitAdapter — split pipeline v7 for GB300 (sm_103)
//   Kernel A (copyconf): out = z stream (2 float4/thread), SKIPPING the
//                        in-domain 16 float4s per row (gemm rewrites them);
//                        per-row softmax conf stats -> g_conf; first 160
//                        blocks also build bf16 transposed weights.
//   Kernel B (gemm):     MLP using g_conf; W1T cp.asyncs issued FIRST so
//                        they hide under the batched feats burst; W1T/W2T
//                        2-deep cp.async pipeline; ldmatrix fragments;
//                        epilogue writes out[in-domain] = z + dz.
// ---------------------------------------------------------------------------

namespace {

constexpr int ROWS_PER_CTA = 128;
constexpr int THREADS      = 256;
constexpr int N_ROWS       = 131072;
constexpr int N_CTAS       = N_ROWS / ROWS_PER_CTA;   // 1024

// smem layout for gemm kernel (bytes)
constexpr unsigned OFF_CF    = 0;         // 128 float4 (pmax,ent,marg,alpha) 2048
constexpr unsigned OFF_DOM   = 2048;      // 128 ints (domain col offset)     512
constexpr unsigned OFF_B1V   = 2560;      // 128 floats (b1)                  512
constexpr unsigned OFF_W256  = 3072;      // 128 floats                       512
constexpr unsigned OFF_W257  = 3584;      // 128 floats                       512
constexpr unsigned OFF_W258  = 4096;      // 128 floats                       512
constexpr unsigned OFF_B2V   = 4608;      // 64 floats                        256
constexpr unsigned OFF_SHA   = 8192;      // 4 chunks x [128 x 128B]        65536
constexpr unsigned OFF_SHB   = 73728;     // 2 chunks x [128 x 128B]        32768
constexpr unsigned SMEM_TOTAL = 106496;   // 104 KB -> 2 CTAs/SM

// Device-global scratch (no allocations allowed)
__device__ __nv_bfloat16 g_W1T[128 * 256];        // [h][f] = W1[f][h], f<256
__device__ __nv_bfloat16 g_W2T[64 * 128];         // [n][h] = W2[h][n]
__device__ __align__(16) float4 g_conf[N_ROWS];   // 2 MB: pmax,ent,marg,alpha

constexpr int PREP_ELEMS  = 128 * 256 + 64 * 128;   // 40960
constexpr int PREP_BLOCKS = PREP_ELEMS / 256;       // 160

__device__ __forceinline__ unsigned swz(unsigned o) { return o ^ ((o >> 3) & 0x70u); }

__device__ __forceinline__ void mma16816(float c[4], const unsigned a[4],
                                         unsigned b0, unsigned b1) {
    asm volatile(
        "mma.sync.aligned.m16n8k16.row.col.f32.bf16.bf16.f32 "
        "{%0,%1,%2,%3}, {%4,%5,%6,%7}, {%8,%9}, {%0,%1,%2,%3};"
        : "+f"(c[0]), "+f"(c[1]), "+f"(c[2]), "+f"(c[3])
        : "r"(a[0]), "r"(a[1]), "r"(a[2]), "r"(a[3]), "r"(b0), "r"(b1));
}

__device__ __forceinline__ void ldsm_x4(unsigned r[4], unsigned addr) {
    asm volatile(
        "ldmatrix.sync.aligned.m8n8.x4.shared.b16 {%0,%1,%2,%3}, [%4];"
        : "=r"(r[0]), "=r"(r[1]), "=r"(r[2]), "=r"(r[3]) : "r"(addr));
}

__device__ __forceinline__ void cp16(unsigned dst, const void* src) {
    asm volatile("cp.async.ca.shared.global [%0], [%1], 16;"
                 :: "r"(dst), "l"(src) : "memory");
}
__device__ __forceinline__ void cp_commit() {
    asm volatile("cp.async.commit_group;" ::: "memory");
}
template <int N>
__device__ __forceinline__ void cp_wait() {
    asm volatile("cp.async.wait_group %0;" :: "n"(N) : "memory");
}

// --------------------------- copy + conf kernel ----------------------------
// grid = 32768; each thread handles TWO float4 elements (t and t+256).
// In-domain elements: conf reduction only (store skipped — gemm owns them).

__device__ __forceinline__ void handle_elem(const float4 v, size_t t,
                                            const int* __restrict__ dom,
                                            const float* __restrict__ alphas,
                                            float4* __restrict__ out4) {
    const int r  = (int)(t >> 7);
    const int c4 = (int)(t & 127u);
    const int d = dom[r];
    const int off4 = d * 16;
    const int rel = c4 - off4;
    if ((unsigned)rel >= 16u) {
        out4[t] = v;                      // out-of-domain: plain copy
        return;
    }
    // in-domain: conf reduction across the 16-thread (half-warp) group
    const unsigned mask = 0xFFFFu << (off4 & 16);
    float hi1 = fmaxf(v.x, v.y), lo1 = fminf(v.x, v.y);
    float hi2 = fmaxf(v.z, v.w), lo2 = fminf(v.z, v.w);
    float m1 = fmaxf(hi1, hi2);
    float m2 = fmaxf(fminf(hi1, hi2), fmaxf(lo1, lo2));
#pragma unroll
    for (int s = 8; s > 0; s >>= 1) {
        float o1 = __shfl_xor_sync(mask, m1, s);
        float o2 = __shfl_xor_sync(mask, m2, s);
        float hi = fmaxf(m1, o1);
        float lo = fmaxf(fminf(m1, o1), fmaxf(m2, o2));
        m1 = hi; m2 = lo;
    }
    const float d0 = v.x - m1, d1 = v.y - m1, d2 = v.z - m1, d3 = v.w - m1;
    const float e0 = expf(d0), e1 = expf(d1), e2 = expf(d2), e3 = expf(d3);
    float S = (e0 + e1) + (e2 + e3);
    float T = (e0 * d0 + e1 * d1) + (e2 * d2 + e3 * d3);
#pragma unroll
    for (int s = 8; s > 0; s >>= 1) {
        S += __shfl_xor_sync(mask, S, s);
        T += __shfl_xor_sync(mask, T, s);
    }
    if (rel == 0) {
        const float inv = 1.0f / S;
        float4 cf;
        cf.x = inv;                          // p_max
        cf.y = logf(S) - T * inv;            // entropy
        cf.z = (1.0f - expf(m2 - m1)) * inv; // margin
        cf.w = alphas[d];
        g_conf[r] = cf;
    }
}

__global__ void __launch_bounds__(256)
copyconf_kernel(const float4* __restrict__ z4, const int* __restrict__ dom,
                const float* __restrict__ alphas,
                const float* __restrict__ W1, const float* __restrict__ W2,
                float4* __restrict__ out4) {
    const size_t t0 = (size_t)blockIdx.x * 512u + threadIdx.x;
    const size_t t1 = t0 + 256u;

    const float4 v0 = z4[t0];
    const float4 v1 = z4[t1];
    handle_elem(v0, t0, dom, alphas, out4);
    handle_elem(v1, t1, dom, alphas, out4);

    // folded prep: first PREP_BLOCKS blocks convert weights to bf16 transposed
    if (blockIdx.x < PREP_BLOCKS) {
        int i = blockIdx.x * 256 + threadIdx.x;
        if (i < 128 * 256) {
            int h = i >> 8, f = i & 255;
            g_W1T[i] = __float2bfloat16(W1[f * 128 + h]);
        } else {
            int i2 = i - 128 * 256;           // < 64*128
            int n = i2 >> 7, h = i2 & 127;
            g_W2T[i2] = __float2bfloat16(W2[h * 64 + n]);
        }
    }
}

// ------------------------------ gemm kernel --------------------------------

__global__ void __launch_bounds__(THREADS, 2)
gemm_kernel(const float* __restrict__ z, const float* __restrict__ feats,
            const float* __restrict__ W1, const float* __restrict__ b1,
            const float* __restrict__ b2, const int* __restrict__ dom,
            float* __restrict__ out) {
    extern __shared__ char smem[];
    const int tid = threadIdx.x;
    const int wid = tid >> 5;
    const int lid = tid & 31;
    const int gid = lid >> 2;    // mma group id (0..7)
    const int tid4 = lid & 3;    // mma thread-in-group (0..3)
    const int row0 = blockIdx.x * ROWS_PER_CTA;
    const unsigned sbase = (unsigned)__cvta_generic_to_shared(smem);

    float4* cF    = (float4*)(smem + OFF_CF);
    int*   domS   = (int*)(smem + OFF_DOM);
    float* b1S    = (float*)(smem + OFF_B1V);
    float* w256S  = (float*)(smem + OFF_W256);
    float* w257S  = (float*)(smem + OFF_W257);
    float* w258S  = (float*)(smem + OFF_W258);
    float* b2S    = (float*)(smem + OFF_B2V);

    // ---- Issue W1T chunks 0,1 via cp.async FIRST — their L2 latency hides
    //      under the feats DRAM burst below.  (16B units preserve SW128.)
    const char* w1tB = (const char*)g_W1T;
#pragma unroll
    for (int pre = 0; pre < 2; pre++) {
#pragma unroll
        for (int u = 0; u < 4; u++) {
            const int j = tid + u * 256;          // 0..1023
            const unsigned hr  = (unsigned)(j >> 3);
            const unsigned off = (unsigned)(j & 7) * 16u;
            cp16(sbase + OFF_SHB + (unsigned)pre * 16384u + swz(hr * 128u + off),
                 w1tB + hr * 512u + (unsigned)pre * 128u + off);
        }
        cp_commit();
    }

    // ---- Phase 0: small staging (conf, dom, bias/conf-weight vectors)
    if (tid < 128) {
        cF[tid]   = g_conf[row0 + tid];
        domS[tid] = dom[row0 + tid] * 64;
        b1S[tid]   = b1[tid];
        w256S[tid] = W1[256 * 128 + tid];
        w257S[tid] = W1[257 * 128 + tid];
        w258S[tid] = W1[258 * 128 + tid];
        if (tid < 64) b2S[tid] = b2[tid];
    }

    // ---- Stage ALL of feats (K=256, 4 chunks, 64KB) -> SHA.
    //      4 batches of 8 back-to-back LDG.128 -> convert -> STS (high MLP).
    {
        const float4* fv = (const float4*)feats + (size_t)row0 * 64;
#pragma unroll 1
        for (int batch = 0; batch < 4; batch++) {
            float4 vb[8];
#pragma unroll
            for (int u = 0; u < 8; u++)
                vb[u] = fv[(size_t)(batch * 8 + u) * 256 + tid];
#pragma unroll
            for (int u = 0; u < 8; u++) {
                const int j = (batch * 8 + u) * 256 + tid;
                const int r = j >> 6, k4 = j & 63;
                const unsigned chunk = (unsigned)(k4 >> 4);
                const unsigned kb = (unsigned)((k4 & 15) << 3);
                __nv_bfloat162 p0 = __floats2bfloat162_rn(vb[u].x, vb[u].y);
                __nv_bfloat162 p1 = __floats2bfloat162_rn(vb[u].z, vb[u].w);
                uint2 w;
                w.x = *(unsigned*)&p0; w.y = *(unsigned*)&p1;
                *(uint2*)(smem + OFF_SHA + chunk * 16384u +
                          swz((unsigned)r * 128u + kb)) = w;
            }
        }
    }

    // ldmatrix lane-address components (within-chunk byte offsets, pre-swizzle)
    const int mrow0 = (wid & 3) * 32;
    const int ncol0 = (wid >> 2) * 64;
    const unsigned laneR  = (unsigned)(lid & 15);
    const unsigned laneHi = (unsigned)(lid >> 4);              // 0/1
    const unsigned offA0 = (unsigned)(mrow0 + laneR) * 128u + laneHi * 16u;
    const unsigned offA1 = offA0 + 16u * 128u;
    const unsigned nLane  = laneHi * 8u + (unsigned)(lid & 7);
    const unsigned colHiB = ((unsigned)(lid >> 3) & 1u) * 16u;

    // GEMM1 accumulators persist across all four K-chunks.
    float acc[2][8][4];
#pragma unroll
    for (int mi = 0; mi < 2; mi++)
#pragma unroll
        for (int ni = 0; ni < 8; ni++)
#pragma unroll
            for (int q = 0; q < 4; q++) acc[mi][ni][q] = 0.0f;

    // ---- GEMM1: 4 K-chunks, 2-deep cp.async pipeline through SHB buffers.
#pragma unroll 1
    for (int kcg = 0; kcg < 4; kcg++) {
        if (kcg < 3) cp_wait<1>(); else cp_wait<0>();
        __syncthreads();   // W1T chunk kcg in its buffer; also covers feats/cF

        const unsigned aB = sbase + OFF_SHA + (unsigned)kcg * 16384u;
        const unsigned bB = sbase + OFF_SHB + (unsigned)(kcg & 1) * 16384u;
#pragma unroll
        for (int ks = 0; ks < 4; ks++) {
            const unsigned kt = (unsigned)ks * 32u;
            unsigned a0[4], a1[4];
            ldsm_x4(a0, aB + swz(offA0 + kt));
            ldsm_x4(a1, aB + swz(offA1 + kt));
#pragma unroll
            for (int j = 0; j < 4; j++) {
                unsigned bb[4];
                const unsigned offB =
                    (unsigned)(ncol0 + j * 16) * 128u + nLane * 128u + colHiB;
                ldsm_x4(bb, bB + swz(offB + kt));
                mma16816(acc[0][2 * j],     a0, bb[0], bb[1]);
                mma16816(acc[1][2 * j],     a1, bb[0], bb[1]);
                mma16816(acc[0][2 * j + 1], a0, bb[2], bb[3]);
                mma16816(acc[1][2 * j + 1], a1, bb[2], bb[3]);
            }
        }
        __syncthreads();   // all warps done reading this buffer

        if (kcg < 2) {     // prefetch chunk kcg+2 into the freed buffer
#pragma unroll
            for (int u = 0; u < 4; u++) {
                const int j = tid + u * 256;
                const unsigned hr  = (unsigned)(j >> 3);
                const unsigned off = (unsigned)(j & 7) * 16u;
                cp16(sbase + OFF_SHB + (unsigned)(kcg & 1) * 16384u +
                         swz(hr * 128u + off),
                     w1tB + hr * 512u + (unsigned)(kcg + 2) * 128u + off);
            }
            cp_commit();
        }
    }

    // ---- Issue W2T cp.async now (dst: SHA chunks 0,1 region — feats dead);
    //      its latency hides under the epilogue-1 ALU below.
    {
        const char* w2tB = (const char*)g_W2T;
#pragma unroll
        for (int u = 0; u < 4; u++) {
            const int j = tid + u * 256;          // 0..1023
            const unsigned nr  = (unsigned)(j >> 4);          // 0..63
            const unsigned c   = ((unsigned)j >> 3) & 1u;     // chunk
            const unsigned off = (unsigned)(j & 7) * 16u;
            cp16(sbase + OFF_SHA + c * 8192u + swz(nr * 128u + off),
                 w2tB + nr * 256u + c * 128u + off);
        }
        cp_commit();
    }

    // ---- Epilogue1: A2 = bf16(relu(h_pre + b1 + c @ W1[256:259])) -> SHB.
    {
#pragma unroll
        for (int mi = 0; mi < 2; mi++) {
            const int rA = mrow0 + mi * 16 + gid;      // rows rA and rA+8
            const float4 cfa = cF[rA];
            const float4 cfb = cF[rA + 8];
#pragma unroll
            for (int ni = 0; ni < 8; ni++) {
                const int j = ncol0 + ni * 8 + tid4 * 2;    // global h col (even)
                const float bj0 = b1S[j],     bj1 = b1S[j + 1];
                const float wa0 = w256S[j],   wa1 = w256S[j + 1];
                const float wb0 = w257S[j],   wb1 = w257S[j + 1];
                const float wc0 = w258S[j],   wc1 = w258S[j + 1];
                float v0 = acc[mi][ni][0] + bj0 + cfa.x * wa0 + cfa.y * wb0 + cfa.z * wc0;
                float v1 = acc[mi][ni][1] + bj1 + cfa.x * wa1 + cfa.y * wb1 + cfa.z * wc1;
                float v2 = acc[mi][ni][2] + bj0 + cfb.x * wa0 + cfb.y * wb0 + cfb.z * wc0;
                float v3 = acc[mi][ni][3] + bj1 + cfb.x * wa1 + cfb.y * wb1 + cfb.z * wc1;
                v0 = fmaxf(v0, 0.0f); v1 = fmaxf(v1, 0.0f);
                v2 = fmaxf(v2, 0.0f); v3 = fmaxf(v3, 0.0f);
                __nv_bfloat162 pA = __floats2bfloat162_rn(v0, v1);
                __nv_bfloat162 pB = __floats2bfloat162_rn(v2, v3);
                const unsigned a2chunk = (unsigned)(wid >> 2) * 16384u;
                const unsigned jb = (unsigned)((ni * 8 + tid4 * 2) * 2);
                *(unsigned*)(smem + OFF_SHB + a2chunk +
                             swz((unsigned)rA * 128u + jb)) = *(unsigned*)&pA;
                *(unsigned*)(smem + OFF_SHB + a2chunk +
                             swz((unsigned)(rA + 8) * 128u + jb)) = *(unsigned*)&pB;
            }
        }
    }
    cp_wait<0>();        // W2T arrived
    __syncthreads();

    // ---- GEMM2  dz[128,64] = h[128,128] @ W2;  A2 in SHB, W2T in SHA.
    {
        const int ncol2 = (wid >> 2) * 32;
        float acc2[2][4][4];
#pragma unroll
        for (int mi = 0; mi < 2; mi++)
#pragma unroll
            for (int ni = 0; ni < 4; ni++)
#pragma unroll
                for (int q = 0; q < 4; q++) acc2[mi][ni][q] = 0.0f;

        // Prefetch epilogue2 z-rereads so their latency hides under the MMAs.
        float2 pzA[2][4], pzB[2][4];
#pragma unroll
        for (int mi = 0; mi < 2; mi++) {
            const int rA = mrow0 + mi * 16 + gid;
            const float* zA = z + (size_t)(row0 + rA) * 512 + domS[rA];
            const float* zB = z + (size_t)(row0 + rA + 8) * 512 + domS[rA + 8];
#pragma unroll
            for (int ni = 0; ni < 4; ni++) {
                const int j = ncol2 + ni * 8 + tid4 * 2;
                pzA[mi][ni] = *(const float2*)(zA + j);
                pzB[mi][ni] = *(const float2*)(zB + j);
            }
        }

#pragma unroll
        for (int kc = 0; kc < 2; kc++) {
            const unsigned aB = sbase + OFF_SHB + (unsigned)kc * 16384u;
            const unsigned bB = sbase + OFF_SHA + (unsigned)kc * 8192u;
#pragma unroll
            for (int ks = 0; ks < 4; ks++) {
                const unsigned kt = (unsigned)ks * 32u;
                unsigned a0[4], a1[4];
                ldsm_x4(a0, aB + swz(offA0 + kt));
                ldsm_x4(a1, aB + swz(offA1 + kt));
#pragma unroll
                for (int j = 0; j < 2; j++) {
                    unsigned bb[4];
                    const unsigned offB =
                        (unsigned)(ncol2 + j * 16) * 128u + nLane * 128u + colHiB;
                    ldsm_x4(bb, bB + swz(offB + kt));
                    mma16816(acc2[0][2 * j],     a0, bb[0], bb[1]);
                    mma16816(acc2[1][2 * j],     a1, bb[0], bb[1]);
                    mma16816(acc2[0][2 * j + 1], a0, bb[2], bb[3]);
                    mma16816(acc2[1][2 * j + 1], a1, bb[2], bb[3]);
                }
            }
        }

        // ---- Epilogue2: out[in-domain] = z + (dz + b2) * alpha.
        //      (copyconf never writes these columns)
#pragma unroll
        for (int mi = 0; mi < 2; mi++) {
            const int rA = mrow0 + mi * 16 + gid;
            const float alA = cF[rA].w;
            const float alB = cF[rA + 8].w;
            float* outA = out + (size_t)(row0 + rA) * 512 + domS[rA];
            float* outB = out + (size_t)(row0 + rA + 8) * 512 + domS[rA + 8];
#pragma unroll
            for (int ni = 0; ni < 4; ni++) {
                const int j = ncol2 + ni * 8 + tid4 * 2;
                const float bj0 = b2S[j], bj1 = b2S[j + 1];
                float2 oA, oB;
                oA.x = pzA[mi][ni].x + (acc2[mi][ni][0] + bj0) * alA;
                oA.y = pzA[mi][ni].y + (acc2[mi][ni][1] + bj1) * alA;
                oB.x = pzB[mi][ni].x + (acc2[mi][ni][2] + bj0) * alB;
                oB.y = pzB[mi][ni].y + (acc2[mi][ni][3] + bj1) * alB;
                *(float2*)(outA + j) = oA;
                *(float2*)(outB + j) = oB;
            }
        }
    }
}

}  // namespace

// ------------------------------ launch -------------------------------------

extern "C" void kernel_launch(void* const* d_in, const int* in_sizes, int n_in,
                              void* d_out, int out_size) {
    const float* z      = (const float*)d_in[0];
    const float* feats  = (const float*)d_in[1];
    const float* W1     = (const float*)d_in[2];
    const float* b1     = (const float*)d_in[3];
    const float* W2     = (const float*)d_in[4];
    const float* b2     = (const float*)d_in[5];
    const float* alphas = (const float*)d_in[6];
    const int*   dom    = (const int*)d_in[7];
    float* out = (float*)d_out;

    cudaFuncSetAttribute(gemm_kernel, cudaFuncAttributeMaxDynamicSharedMemorySize,
                         SMEM_TOTAL);

    copyconf_kernel<<<N_ROWS * 128 / 512, 256>>>((const float4*)z, dom, alphas,
                                                 W1, W2, (float4*)out);
    gemm_kernel<<<N_CTAS, THREADS, SMEM_TOTAL>>>(z, feats, W1, b1, b2, dom, out);
}

// round 16
// speedup vs baseline: 1.2628x; 1.0104x over previous
#include <cuda_runtime.h>
#include <cuda_bf16.h>
#include <cstdint>

// ---------------------------------------------------------------------------
// ResidualLogitAdapter — split pipeline v8 for GB300 (sm_103)
//   Kernel A (copyconf): out = z stream (2 float4/thread), SKIPPING the
//                        in-domain 16 float4s per row (gemm rewrites them);
//                        per-row softmax conf stats -> g_conf; first 160
//                        blocks also build bf16 transposed weights.
//   Kernel B (gemm):     PERSISTENT CTAs (grid=296, 2/SM) loop over work
//                        tiles — no wave-quantization tail; loop-invariant
//                        vectors staged once.  Per tile: W1T/W2T cp.async
//                        pipeline, ldmatrix fragments, epilogue writes
//                        out[in-domain] = z + dz.
// ---------------------------------------------------------------------------

namespace {

constexpr int ROWS_PER_CTA = 128;
constexpr int THREADS      = 256;
constexpr int N_ROWS       = 131072;
constexpr int N_WORK       = N_ROWS / ROWS_PER_CTA;   // 1024
constexpr int GEMM_CTAS    = 296;                     // 148 SMs x 2

// smem layout for gemm kernel (bytes)
constexpr unsigned OFF_CF    = 0;         // 128 float4 (pmax,ent,marg,alpha) 2048
constexpr unsigned OFF_DOM   = 2048;      // 128 ints (domain col offset)     512
constexpr unsigned OFF_B1V   = 2560;      // 128 floats (b1)                  512
constexpr unsigned OFF_W256  = 3072;      // 128 floats                       512
constexpr unsigned OFF_W257  = 3584;      // 128 floats                       512
constexpr unsigned OFF_W258  = 4096;      // 128 floats                       512
constexpr unsigned OFF_B2V   = 4608;      // 64 floats                        256
constexpr unsigned OFF_SHA   = 8192;      // 4 chunks x [128 x 128B]        65536
constexpr unsigned OFF_SHB   = 73728;     // 2 chunks x [128 x 128B]        32768
constexpr unsigned SMEM_TOTAL = 106496;   // 104 KB -> 2 CTAs/SM

// Device-global scratch (no allocations allowed)
__device__ __nv_bfloat16 g_W1T[128 * 256];        // [h][f] = W1[f][h], f<256
__device__ __nv_bfloat16 g_W2T[64 * 128];         // [n][h] = W2[h][n]
__device__ __align__(16) float4 g_conf[N_ROWS];   // 2 MB: pmax,ent,marg,alpha

constexpr int PREP_ELEMS  = 128 * 256 + 64 * 128;   // 40960
constexpr int PREP_BLOCKS = PREP_ELEMS / 256;       // 160

__device__ __forceinline__ unsigned swz(unsigned o) { return o ^ ((o >> 3) & 0x70u); }

__device__ __forceinline__ void mma16816(float c[4], const unsigned a[4],
                                         unsigned b0, unsigned b1) {
    asm volatile(
        "mma.sync.aligned.m16n8k16.row.col.f32.bf16.bf16.f32 "
        "{%0,%1,%2,%3}, {%4,%5,%6,%7}, {%8,%9}, {%0,%1,%2,%3};"
        : "+f"(c[0]), "+f"(c[1]), "+f"(c[2]), "+f"(c[3])
        : "r"(a[0]), "r"(a[1]), "r"(a[2]), "r"(a[3]), "r"(b0), "r"(b1));
}

__device__ __forceinline__ void ldsm_x4(unsigned r[4], unsigned addr) {
    asm volatile(
        "ldmatrix.sync.aligned.m8n8.x4.shared.b16 {%0,%1,%2,%3}, [%4];"
        : "=r"(r[0]), "=r"(r[1]), "=r"(r[2]), "=r"(r[3]) : "r"(addr));
}

__device__ __forceinline__ void cp16(unsigned dst, const void* src) {
    asm volatile("cp.async.ca.shared.global [%0], [%1], 16;"
                 :: "r"(dst), "l"(src) : "memory");
}
__device__ __forceinline__ void cp_commit() {
    asm volatile("cp.async.commit_group;" ::: "memory");
}
template <int N>
__device__ __forceinline__ void cp_wait() {
    asm volatile("cp.async.wait_group %0;" :: "n"(N) : "memory");
}

// --------------------------- copy + conf kernel ----------------------------
// grid = 32768; each thread handles TWO float4 elements (t and t+256).
// In-domain elements: conf reduction only (store skipped — gemm owns them).

__device__ __forceinline__ void handle_elem(const float4 v, size_t t,
                                            const int* __restrict__ dom,
                                            const float* __restrict__ alphas,
                                            float4* __restrict__ out4) {
    const int r  = (int)(t >> 7);
    const int c4 = (int)(t & 127u);
    const int d = dom[r];
    const int off4 = d * 16;
    const int rel = c4 - off4;
    if ((unsigned)rel >= 16u) {
        out4[t] = v;                      // out-of-domain: plain copy
        return;
    }
    // in-domain: conf reduction across the 16-thread (half-warp) group
    const unsigned mask = 0xFFFFu << (off4 & 16);
    float hi1 = fmaxf(v.x, v.y), lo1 = fminf(v.x, v.y);
    float hi2 = fmaxf(v.z, v.w), lo2 = fminf(v.z, v.w);
    float m1 = fmaxf(hi1, hi2);
    float m2 = fmaxf(fminf(hi1, hi2), fmaxf(lo1, lo2));
#pragma unroll
    for (int s = 8; s > 0; s >>= 1) {
        float o1 = __shfl_xor_sync(mask, m1, s);
        float o2 = __shfl_xor_sync(mask, m2, s);
        float hi = fmaxf(m1, o1);
        float lo = fmaxf(fminf(m1, o1), fmaxf(m2, o2));
        m1 = hi; m2 = lo;
    }
    const float d0 = v.x - m1, d1 = v.y - m1, d2 = v.z - m1, d3 = v.w - m1;
    const float e0 = expf(d0), e1 = expf(d1), e2 = expf(d2), e3 = expf(d3);
    float S = (e0 + e1) + (e2 + e3);
    float T = (e0 * d0 + e1 * d1) + (e2 * d2 + e3 * d3);
#pragma unroll
    for (int s = 8; s > 0; s >>= 1) {
        S += __shfl_xor_sync(mask, S, s);
        T += __shfl_xor_sync(mask, T, s);
    }
    if (rel == 0) {
        const float inv = 1.0f / S;
        float4 cf;
        cf.x = inv;                          // p_max
        cf.y = logf(S) - T * inv;            // entropy
        cf.z = (1.0f - expf(m2 - m1)) * inv; // margin
        cf.w = alphas[d];
        g_conf[r] = cf;
    }
}

__global__ void __launch_bounds__(256)
copyconf_kernel(const float4* __restrict__ z4, const int* __restrict__ dom,
                const float* __restrict__ alphas,
                const float* __restrict__ W1, const float* __restrict__ W2,
                float4* __restrict__ out4) {
    const size_t t0 = (size_t)blockIdx.x * 512u + threadIdx.x;
    const size_t t1 = t0 + 256u;

    const float4 v0 = z4[t0];
    const float4 v1 = z4[t1];
    handle_elem(v0, t0, dom, alphas, out4);
    handle_elem(v1, t1, dom, alphas, out4);

    // folded prep: first PREP_BLOCKS blocks convert weights to bf16 transposed
    if (blockIdx.x < PREP_BLOCKS) {
        int i = blockIdx.x * 256 + threadIdx.x;
        if (i < 128 * 256) {
            int h = i >> 8, f = i & 255;
            g_W1T[i] = __float2bfloat16(W1[f * 128 + h]);
        } else {
            int i2 = i - 128 * 256;           // < 64*128
            int n = i2 >> 7, h = i2 & 127;
            g_W2T[i2] = __float2bfloat16(W2[h * 64 + n]);
        }
    }
}

// ------------------------------ gemm kernel --------------------------------
// Persistent: grid = 296 (2 CTAs/SM); each CTA loops over work tiles.

__global__ void __launch_bounds__(THREADS, 2)
gemm_kernel(const float* __restrict__ z, const float* __restrict__ feats,
            const float* __restrict__ W1, const float* __restrict__ b1,
            const float* __restrict__ b2, const int* __restrict__ dom,
            float* __restrict__ out) {
    extern __shared__ char smem[];
    const int tid = threadIdx.x;
    const int wid = tid >> 5;
    const int lid = tid & 31;
    const int gid = lid >> 2;    // mma group id (0..7)
    const int tid4 = lid & 3;    // mma thread-in-group (0..3)
    const unsigned sbase = (unsigned)__cvta_generic_to_shared(smem);

    float4* cF    = (float4*)(smem + OFF_CF);
    int*   domS   = (int*)(smem + OFF_DOM);
    float* b1S    = (float*)(smem + OFF_B1V);
    float* w256S  = (float*)(smem + OFF_W256);
    float* w257S  = (float*)(smem + OFF_W257);
    float* w258S  = (float*)(smem + OFF_W258);
    float* b2S    = (float*)(smem + OFF_B2V);

    // ---- Loop-invariant staging: bias + conf-weight vectors (once per CTA)
    if (tid < 128) {
        b1S[tid]   = b1[tid];
        w256S[tid] = W1[256 * 128 + tid];
        w257S[tid] = W1[257 * 128 + tid];
        w258S[tid] = W1[258 * 128 + tid];
        if (tid < 64) b2S[tid] = b2[tid];
    }

    // ldmatrix lane-address components (within-chunk byte offsets, pre-swizzle)
    const int mrow0 = (wid & 3) * 32;
    const int ncol0 = (wid >> 2) * 64;
    const unsigned laneR  = (unsigned)(lid & 15);
    const unsigned laneHi = (unsigned)(lid >> 4);              // 0/1
    const unsigned offA0 = (unsigned)(mrow0 + laneR) * 128u + laneHi * 16u;
    const unsigned offA1 = offA0 + 16u * 128u;
    const unsigned nLane  = laneHi * 8u + (unsigned)(lid & 7);
    const unsigned colHiB = ((unsigned)(lid >> 3) & 1u) * 16u;

    const char* w1tB = (const char*)g_W1T;
    const char* w2tB = (const char*)g_W2T;

    for (int work = blockIdx.x; work < N_WORK; work += GEMM_CTAS) {
        const int row0 = work * ROWS_PER_CTA;

        // ---- W1T chunks 0,1 via cp.async FIRST — hide under the feats burst.
#pragma unroll
        for (int pre = 0; pre < 2; pre++) {
#pragma unroll
            for (int u = 0; u < 4; u++) {
                const int j = tid + u * 256;          // 0..1023
                const unsigned hr  = (unsigned)(j >> 3);
                const unsigned off = (unsigned)(j & 7) * 16u;
                cp16(sbase + OFF_SHB + (unsigned)pre * 16384u + swz(hr * 128u + off),
                     w1tB + hr * 512u + (unsigned)pre * 128u + off);
            }
            cp_commit();
        }

        // ---- Per-tile small staging (conf, dom)
        if (tid < 128) {
            cF[tid]   = g_conf[row0 + tid];
            domS[tid] = dom[row0 + tid] * 64;
        }

        // ---- Stage ALL of feats (K=256, 4 chunks, 64KB) -> SHA.
        //      4 batches of 8 back-to-back LDG.128 -> convert -> STS.
        {
            const float4* fv = (const float4*)feats + (size_t)row0 * 64;
#pragma unroll 1
            for (int batch = 0; batch < 4; batch++) {
                float4 vb[8];
#pragma unroll
                for (int u = 0; u < 8; u++)
                    vb[u] = fv[(size_t)(batch * 8 + u) * 256 + tid];
#pragma unroll
                for (int u = 0; u < 8; u++) {
                    const int j = (batch * 8 + u) * 256 + tid;
                    const int r = j >> 6, k4 = j & 63;
                    const unsigned chunk = (unsigned)(k4 >> 4);
                    const unsigned kb = (unsigned)((k4 & 15) << 3);
                    __nv_bfloat162 p0 = __floats2bfloat162_rn(vb[u].x, vb[u].y);
                    __nv_bfloat162 p1 = __floats2bfloat162_rn(vb[u].z, vb[u].w);
                    uint2 w;
                    w.x = *(unsigned*)&p0; w.y = *(unsigned*)&p1;
                    *(uint2*)(smem + OFF_SHA + chunk * 16384u +
                              swz((unsigned)r * 128u + kb)) = w;
                }
            }
        }

        // GEMM1 accumulators persist across all four K-chunks.
        float acc[2][8][4];
#pragma unroll
        for (int mi = 0; mi < 2; mi++)
#pragma unroll
            for (int ni = 0; ni < 8; ni++)
#pragma unroll
                for (int q = 0; q < 4; q++) acc[mi][ni][q] = 0.0f;

        // ---- GEMM1: 4 K-chunks, 2-deep cp.async pipeline through SHB.
#pragma unroll 1
        for (int kcg = 0; kcg < 4; kcg++) {
            if (kcg < 3) cp_wait<1>(); else cp_wait<0>();
            __syncthreads();   // W1T chunk kcg ready; also covers feats/cF

            const unsigned aB = sbase + OFF_SHA + (unsigned)kcg * 16384u;
            const unsigned bB = sbase + OFF_SHB + (unsigned)(kcg & 1) * 16384u;
#pragma unroll
            for (int ks = 0; ks < 4; ks++) {
                const unsigned kt = (unsigned)ks * 32u;
                unsigned a0[4], a1[4];
                ldsm_x4(a0, aB + swz(offA0 + kt));
                ldsm_x4(a1, aB + swz(offA1 + kt));
#pragma unroll
                for (int j = 0; j < 4; j++) {
                    unsigned bb[4];
                    const unsigned offB =
                        (unsigned)(ncol0 + j * 16) * 128u + nLane * 128u + colHiB;
                    ldsm_x4(bb, bB + swz(offB + kt));
                    mma16816(acc[0][2 * j],     a0, bb[0], bb[1]);
                    mma16816(acc[1][2 * j],     a1, bb[0], bb[1]);
                    mma16816(acc[0][2 * j + 1], a0, bb[2], bb[3]);
                    mma16816(acc[1][2 * j + 1], a1, bb[2], bb[3]);
                }
            }
            __syncthreads();   // all warps done reading this buffer

            if (kcg < 2) {     // prefetch chunk kcg+2 into the freed buffer
#pragma unroll
                for (int u = 0; u < 4; u++) {
                    const int j = tid + u * 256;
                    const unsigned hr  = (unsigned)(j >> 3);
                    const unsigned off = (unsigned)(j & 7) * 16u;
                    cp16(sbase + OFF_SHB + (unsigned)(kcg & 1) * 16384u +
                             swz(hr * 128u + off),
                         w1tB + hr * 512u + (unsigned)(kcg + 2) * 128u + off);
                }
                cp_commit();
            }
        }

        // ---- Issue W2T cp.async (dst: SHA chunks 0,1 — feats dead);
        //      latency hides under the epilogue-1 ALU below.
        {
#pragma unroll
            for (int u = 0; u < 4; u++) {
                const int j = tid + u * 256;          // 0..1023
                const unsigned nr  = (unsigned)(j >> 4);          // 0..63
                const unsigned c   = ((unsigned)j >> 3) & 1u;     // chunk
                const unsigned off = (unsigned)(j & 7) * 16u;
                cp16(sbase + OFF_SHA + c * 8192u + swz(nr * 128u + off),
                     w2tB + nr * 256u + c * 128u + off);
            }
            cp_commit();
        }

        // ---- Epilogue1: A2 = bf16(relu(h_pre + b1 + c @ W1[256:259])) -> SHB.
        {
#pragma unroll
            for (int mi = 0; mi < 2; mi++) {
                const int rA = mrow0 + mi * 16 + gid;      // rows rA and rA+8
                const float4 cfa = cF[rA];
                const float4 cfb = cF[rA + 8];
#pragma unroll
                for (int ni = 0; ni < 8; ni++) {
                    const int j = ncol0 + ni * 8 + tid4 * 2;    // h col (even)
                    const float bj0 = b1S[j],     bj1 = b1S[j + 1];
                    const float wa0 = w256S[j],   wa1 = w256S[j + 1];
                    const float wb0 = w257S[j],   wb1 = w257S[j + 1];
                    const float wc0 = w258S[j],   wc1 = w258S[j + 1];
                    float v0 = acc[mi][ni][0] + bj0 + cfa.x * wa0 + cfa.y * wb0 + cfa.z * wc0;
                    float v1 = acc[mi][ni][1] + bj1 + cfa.x * wa1 + cfa.y * wb1 + cfa.z * wc1;
                    float v2 = acc[mi][ni][2] + bj0 + cfb.x * wa0 + cfb.y * wb0 + cfb.z * wc0;
                    float v3 = acc[mi][ni][3] + bj1 + cfb.x * wa1 + cfb.y * wb1 + cfb.z * wc1;
                    v0 = fmaxf(v0, 0.0f); v1 = fmaxf(v1, 0.0f);
                    v2 = fmaxf(v2, 0.0f); v3 = fmaxf(v3, 0.0f);
                    __nv_bfloat162 pA = __floats2bfloat162_rn(v0, v1);
                    __nv_bfloat162 pB = __floats2bfloat162_rn(v2, v3);
                    const unsigned a2chunk = (unsigned)(wid >> 2) * 16384u;
                    const unsigned jb = (unsigned)((ni * 8 + tid4 * 2) * 2);
                    *(unsigned*)(smem + OFF_SHB + a2chunk +
                                 swz((unsigned)rA * 128u + jb)) = *(unsigned*)&pA;
                    *(unsigned*)(smem + OFF_SHB + a2chunk +
                                 swz((unsigned)(rA + 8) * 128u + jb)) = *(unsigned*)&pB;
                }
            }
        }
        cp_wait<0>();        // W2T arrived
        __syncthreads();

        // ---- GEMM2  dz[128,64] = h[128,128] @ W2;  A2 in SHB, W2T in SHA.
        {
            const int ncol2 = (wid >> 2) * 32;
            float acc2[2][4][4];
#pragma unroll
            for (int mi = 0; mi < 2; mi++)
#pragma unroll
                for (int ni = 0; ni < 4; ni++)
#pragma unroll
                    for (int q = 0; q < 4; q++) acc2[mi][ni][q] = 0.0f;

            // Prefetch epilogue2 z-rereads; latency hides under the MMAs.
            float2 pzA[2][4], pzB[2][4];
#pragma unroll
            for (int mi = 0; mi < 2; mi++) {
                const int rA = mrow0 + mi * 16 + gid;
                const float* zA = z + (size_t)(row0 + rA) * 512 + domS[rA];
                const float* zB = z + (size_t)(row0 + rA + 8) * 512 + domS[rA + 8];
#pragma unroll
                for (int ni = 0; ni < 4; ni++) {
                    const int j = ncol2 + ni * 8 + tid4 * 2;
                    pzA[mi][ni] = *(const float2*)(zA + j);
                    pzB[mi][ni] = *(const float2*)(zB + j);
                }
            }

#pragma unroll
            for (int kc = 0; kc < 2; kc++) {
                const unsigned aB = sbase + OFF_SHB + (unsigned)kc * 16384u;
                const unsigned bB = sbase + OFF_SHA + (unsigned)kc * 8192u;
#pragma unroll
                for (int ks = 0; ks < 4; ks++) {
                    const unsigned kt = (unsigned)ks * 32u;
                    unsigned a0[4], a1[4];
                    ldsm_x4(a0, aB + swz(offA0 + kt));
                    ldsm_x4(a1, aB + swz(offA1 + kt));
#pragma unroll
                    for (int j = 0; j < 2; j++) {
                        unsigned bb[4];
                        const unsigned offB =
                            (unsigned)(ncol2 + j * 16) * 128u + nLane * 128u + colHiB;
                        ldsm_x4(bb, bB + swz(offB + kt));
                        mma16816(acc2[0][2 * j],     a0, bb[0], bb[1]);
                        mma16816(acc2[1][2 * j],     a1, bb[0], bb[1]);
                        mma16816(acc2[0][2 * j + 1], a0, bb[2], bb[3]);
                        mma16816(acc2[1][2 * j + 1], a1, bb[2], bb[3]);
                    }
                }
            }

            // ---- Epilogue2: out[in-domain] = z + (dz + b2) * alpha.
#pragma unroll
            for (int mi = 0; mi < 2; mi++) {
                const int rA = mrow0 + mi * 16 + gid;
                const float alA = cF[rA].w;
                const float alB = cF[rA + 8].w;
                float* outA = out + (size_t)(row0 + rA) * 512 + domS[rA];
                float* outB = out + (size_t)(row0 + rA + 8) * 512 + domS[rA + 8];
#pragma unroll
                for (int ni = 0; ni < 4; ni++) {
                    const int j = ncol2 + ni * 8 + tid4 * 2;
                    const float bj0 = b2S[j], bj1 = b2S[j + 1];
                    float2 oA, oB;
                    oA.x = pzA[mi][ni].x + (acc2[mi][ni][0] + bj0) * alA;
                    oA.y = pzA[mi][ni].y + (acc2[mi][ni][1] + bj1) * alA;
                    oB.x = pzB[mi][ni].x + (acc2[mi][ni][2] + bj0) * alB;
                    oB.y = pzB[mi][ni].y + (acc2[mi][ni][3] + bj1) * alB;
                    *(float2*)(outA + j) = oA;
                    *(float2*)(outB + j) = oB;
                }
            }
        }

        // All warps done reading SHA/SHB/cF/domS before next tile's writes.
        __syncthreads();
    }
}

}  // namespace

// ------------------------------ launch -------------------------------------

extern "C" void kernel_launch(void* const* d_in, const int* in_sizes, int n_in,
                              void* d_out, int out_size) {
    const float* z      = (const float*)d_in[0];
    const float* feats  = (const float*)d_in[1];
    const float* W1     = (const float*)d_in[2];
    const float* b1     = (const float*)d_in[3];
    const float* W2     = (const float*)d_in[4];
    const float* b2     = (const float*)d_in[5];
    const float* alphas = (const float*)d_in[6];
    const int*   dom    = (const int*)d_in[7];
    float* out = (float*)d_out;

    cudaFuncSetAttribute(gemm_kernel, cudaFuncAttributeMaxDynamicSharedMemorySize,
                         SMEM_TOTAL);

    copyconf_kernel<<<N_ROWS * 128 / 512, 256>>>((const float4*)z, dom, alphas,
                                                 W1, W2, (float4*)out);
    gemm_kernel<<<GEMM_CTAS, THREADS, SMEM_TOTAL>>>(z, feats, W1, b1, b2, dom, out);
}